// round 4
// baseline (speedup 1.0000x reference)
#include <cuda_runtime.h>

// Problem constants (fixed by the dataset shapes)
#define DIMS 1024           // embedding dim, fp32
#define VECS_PER_ROW 256    // 1024 floats / 4 per float4
#define MAX_PAIRS 8192
#define VOCAB 50257

#define EPS 1e-8f
#define WEIGHT 0.01f

// Scratch: per-pair cosine similarity (allocation-free __device__ global)
__device__ float g_sims[MAX_PAIRS];

// Kernel 1: one CTA per pair. 256 threads; thread t loads float4 #t of each
// gathered row (one LDG.128 per row), accumulates dot / |a|^2 / |m|^2,
// then a shuffle+smem block reduction.
__global__ __launch_bounds__(VECS_PER_ROW) void pair_cosine_kernel(
    const float* __restrict__ W,
    const int* __restrict__ archaic_idx,   // JAX int64 request silently becomes int32
    const int* __restrict__ modern_idx)
{
    const int p = blockIdx.x;
    const int t = threadIdx.x;

    // Clamp defensively: if the dtype assumption is wrong we want a finite
    // wrong answer (diagnosable rel_err), not an illegal access.
    int ai = __ldg(archaic_idx + p);
    int mi = __ldg(modern_idx + p);
    ai = min(max(ai, 0), VOCAB - 1);
    mi = min(max(mi, 0), VOCAB - 1);

    const float4* __restrict__ a4 =
        reinterpret_cast<const float4*>(W + (size_t)ai * DIMS);
    const float4* __restrict__ m4 =
        reinterpret_cast<const float4*>(W + (size_t)mi * DIMS);

    const float4 av = a4[t];
    const float4 mv = m4[t];

    float dot = av.x * mv.x + av.y * mv.y + av.z * mv.z + av.w * mv.w;
    float na  = av.x * av.x + av.y * av.y + av.z * av.z + av.w * av.w;
    float nm  = mv.x * mv.x + mv.y * mv.y + mv.z * mv.z + mv.w * mv.w;

    // Warp-level reduce (32 lanes)
    #pragma unroll
    for (int off = 16; off > 0; off >>= 1) {
        dot += __shfl_down_sync(0xFFFFFFFFu, dot, off);
        na  += __shfl_down_sync(0xFFFFFFFFu, na,  off);
        nm  += __shfl_down_sync(0xFFFFFFFFu, nm,  off);
    }

    __shared__ float s_dot[8], s_na[8], s_nm[8];
    const int warp = t >> 5;
    const int lane = t & 31;
    if (lane == 0) {
        s_dot[warp] = dot;
        s_na[warp]  = na;
        s_nm[warp]  = nm;
    }
    __syncthreads();

    if (warp == 0) {
        dot = (lane < 8) ? s_dot[lane] : 0.0f;
        na  = (lane < 8) ? s_na[lane]  : 0.0f;
        nm  = (lane < 8) ? s_nm[lane]  : 0.0f;
        #pragma unroll
        for (int off = 4; off > 0; off >>= 1) {
            dot += __shfl_down_sync(0xFFFFFFFFu, dot, off);
            na  += __shfl_down_sync(0xFFFFFFFFu, na,  off);
            nm  += __shfl_down_sync(0xFFFFFFFFu, nm,  off);
        }
        if (lane == 0) {
            const float den = fmaxf(sqrtf(na), EPS) * fmaxf(sqrtf(nm), EPS);
            g_sims[p] = dot / den;
        }
    }
}

// Kernel 2: single CTA, deterministic tree reduction of the n_pairs sims.
__global__ __launch_bounds__(256) void loss_reduce_kernel(float* __restrict__ out, int n)
{
    const int t = threadIdx.x;
    float s = 0.0f;
    for (int i = t; i < n; i += 256)
        s += 1.0f - g_sims[i];

    #pragma unroll
    for (int off = 16; off > 0; off >>= 1)
        s += __shfl_down_sync(0xFFFFFFFFu, s, off);

    __shared__ float s_part[8];
    const int warp = t >> 5;
    const int lane = t & 31;
    if (lane == 0) s_part[warp] = s;
    __syncthreads();

    if (warp == 0) {
        s = (lane < 8) ? s_part[lane] : 0.0f;
        #pragma unroll
        for (int off = 4; off > 0; off >>= 1)
            s += __shfl_down_sync(0xFFFFFFFFu, s, off);
        if (lane == 0)
            out[0] = WEIGHT * (s / (float)n);
    }
}

extern "C" void kernel_launch(void* const* d_in, const int* in_sizes, int n_in,
                              void* d_out, int out_size)
{
    const float* W  = (const float*)d_in[0];   // [50257, 1024] fp32
    const int*   ai = (const int*)d_in[1];     // [n_pairs] int32
    const int*   mi = (const int*)d_in[2];     // [n_pairs] int32
    float* out = (float*)d_out;

    int n_pairs = in_sizes[1];
    if (n_pairs > MAX_PAIRS) n_pairs = MAX_PAIRS;
    if (n_pairs < 1) n_pairs = 1;

    pair_cosine_kernel<<<n_pairs, VECS_PER_ROW>>>(W, ai, mi);
    loss_reduce_kernel<<<1, 256>>>(out, n_pairs);
}